// round 2
// baseline (speedup 1.0000x reference)
#include <cuda_runtime.h>
#include <math.h>

#define NN 100000
#define NNBR 12
#define NE (NN*NNBR)
#define CD 192
#define KD 64
#define NBINS 1024
#define NB4 256
#define BN_EPS 1e-5f

// ---------------- scratch (static __device__, no allocs) ----------------
__device__ float g_PD[(size_t)NN*CD];    // per-node dst-side partial (+bias)
__device__ float g_PS[(size_t)NN*CD];    // per-node src-side partial
__device__ float g_U [(size_t)NE*CD];    // pre-BN edge outputs (921.6 MB)
__device__ float g_binS[NBINS*CD];
__device__ float g_binQ[NBINS*CD];
__device__ float g_scale[CD];
__device__ float g_shift[CD];
__device__ float g_nbr[NN*KD];
__device__ float g_b4S[NB4*KD];
__device__ float g_b4Q[NB4*KD];
__device__ float g_scale4[KD];
__device__ float g_shift4[KD];
__device__ int   g_is64;                 // edge_index dtype flag (runtime-detected)

// packed f32x2 FMA: d = a*b + d  (2x fp32 throughput on sm_103a)
__device__ __forceinline__ void ffma2(float2 &d, float2 a, float2 b) {
    asm("fma.rn.f32x2 %0, %1, %2, %0;"
        : "+l"(reinterpret_cast<unsigned long long&>(d))
        : "l"(reinterpret_cast<unsigned long long&>(a)),
          "l"(reinterpret_cast<unsigned long long&>(b)));
}

__device__ __forceinline__ float softplus_f(float x) {
    return fmaxf(x, 0.f) + log1pf(__expf(-fabsf(x)));
}
__device__ __forceinline__ float sigmoid_f(float x) {
    return 1.f / (1.f + __expf(-x));
}

// ---------------- K0: zero stat buffers + detect index dtype ----------------
__global__ void kzero(const int* __restrict__ eidx32) {
    int i = blockIdx.x * blockDim.x + threadIdx.x;
    if (i < NBINS*CD) { g_binS[i] = 0.f; g_binQ[i] = 0.f; }
    if (i < NB4*KD)   { g_b4S[i]  = 0.f; g_b4Q[i]  = 0.f; }
    if (i == 0) {
        // src = repeat(arange(N), 12). If buffer is int64 (little-endian),
        // int32-word 25 is the high half of src[12]=1 -> 0.
        // If buffer is int32, word 25 = src[25] = 2 (nonzero).
        g_is64 = (eidx32[25] == 0) ? 1 : 0;
    }
}

// ---------------- K1: node pre-GEMM  PD/PS = x @ Wparts^T ----------------
// blockDim (96,2): ty selects one group of 8 nodes; thread owns cols j, j+96.
#define K1_SMEM (64*384*4 + 2*64*8*4)
__global__ void k1_nodegemm(const float* __restrict__ x,
                            const float* __restrict__ Wc, const float* __restrict__ bc,
                            const float* __restrict__ Wf, const float* __restrict__ bf,
                            const float* __restrict__ Wb, const float* __restrict__ bb)
{
    extern __shared__ float sm[];
    float* sW = sm;             // [64][384]: [k][j] dst-part, [k][192+j] src-part
    float* sX = sm + 64*384;    // [2][64][8] node-pair-major
    int tx = threadIdx.x, ty = threadIdx.y;
    int tid = ty*96 + tx;

    for (int idx = tid; idx < 64*384; idx += 192) {
        int k  = idx / 384;
        int j3 = idx - k*384;
        int j  = (j3 >= 192) ? j3 - 192 : j3;
        int kk = (j3 >= 192) ? 64 + k : k;
        const float* W; int r;
        if (j < 64)       { W = Wc; r = j; }
        else if (j < 128) { W = Wf; r = j - 64; }
        else              { W = Wb; r = j - 128; }
        sW[idx] = W[r*CD + kk];
    }
    int ng = blockIdx.x*2 + ty;
    int n0 = ng * 8;
    float* sXt = sX + ty*512;
    for (int idx = tx; idx < 8*64; idx += 96) {
        int nl = idx >> 6, k = idx & 63;
        sXt[k*8 + nl] = x[(size_t)(n0+nl)*64 + k];
    }
    __syncthreads();

    float2 ad0[4], ad1[4], as0[4], as1[4];
    #pragma unroll
    for (int p = 0; p < 4; p++) {
        ad0[p] = make_float2(0.f,0.f); ad1[p] = make_float2(0.f,0.f);
        as0[p] = make_float2(0.f,0.f); as1[p] = make_float2(0.f,0.f);
    }
    int j0 = tx, j1 = tx + 96;
    #pragma unroll 8
    for (int k = 0; k < 64; k++) {
        float wd0 = sW[k*384 + j0];
        float wd1 = sW[k*384 + j1];
        float ws0 = sW[k*384 + 192 + j0];
        float ws1 = sW[k*384 + 192 + j1];
        float2 Wd0 = make_float2(wd0, wd0), Wd1 = make_float2(wd1, wd1);
        float2 Ws0 = make_float2(ws0, ws0), Ws1 = make_float2(ws1, ws1);
        const float2* xp = (const float2*)(sXt + k*8);
        #pragma unroll
        for (int p = 0; p < 4; p++) {
            float2 xv = xp[p];
            ffma2(ad0[p], xv, Wd0);
            ffma2(ad1[p], xv, Wd1);
            ffma2(as0[p], xv, Ws0);
            ffma2(as1[p], xv, Ws1);
        }
    }
    float bias0 = (j0 < 64) ? bc[j0] : ((j0 < 128) ? bf[j0-64] : bb[j0-128]);
    float bias1 = (j1 < 128) ? bf[j1-64] : bb[j1-128];
    #pragma unroll
    for (int p = 0; p < 4; p++) {
        size_t na = (size_t)(n0 + 2*p)*CD, nb = na + CD;
        g_PD[na + j0] = ad0[p].x + bias0;
        g_PD[nb + j0] = ad0[p].y + bias0;
        g_PD[na + j1] = ad1[p].x + bias1;
        g_PD[nb + j1] = ad1[p].y + bias1;
        g_PS[na + j0] = as0[p].x;
        g_PS[nb + j0] = as0[p].y;
        g_PS[na + j1] = as1[p].x;
        g_PS[nb + j1] = as1[p].y;
    }
}

// ---------------- K2: edge GEMM + gathers -> U, binned BN stats ----------
// blockDim (96,2): ty handles one node's 12 edges; thread owns cols j, j+96.
#define K2_SMEM (64*192*4 + 2*64*12*4 + 2*24*4)
__global__ void k2_edge(const float* __restrict__ ea,
                        const void* __restrict__ eidx_raw,
                        const float* __restrict__ Wc,
                        const float* __restrict__ Wf,
                        const float* __restrict__ Wb)
{
    extern __shared__ float sm[];
    float* sW  = sm;                  // [64][192]  edge-part of W, [k][j]
    float* sEA = sm + 64*192;         // [2][64][12]
    int*   sIdx = (int*)(sEA + 2*64*12);  // [2][24]: 0..11 dst, 12..23 src
    int tx = threadIdx.x, ty = threadIdx.y;
    int tid = ty*96 + tx;

    for (int idx = tid; idx < 64*192; idx += 192) {
        int k = idx / 192;
        int j = idx - k*192;
        const float* W; int r;
        if (j < 64)       { W = Wc; r = j; }
        else if (j < 128) { W = Wf; r = j - 64; }
        else              { W = Wb; r = j - 128; }
        sW[idx] = W[r*CD + 128 + k];
    }
    int n  = blockIdx.x*2 + ty;
    int e0 = n * NNBR;
    float* sEAt = sEA + ty*768;
    for (int idx = tx; idx < 768; idx += 96) {
        int el = idx >> 6, k = idx & 63;
        sEAt[k*12 + el] = ea[(size_t)(e0+el)*64 + k];
    }
    if (tx < 24) {
        // tx<12 -> dst indices (edge_index[1]); tx in [12,24) -> src (edge_index[0])
        size_t pos = (tx < 12) ? ((size_t)NE + e0 + tx) : ((size_t)e0 + tx - 12);
        int v;
        if (g_is64) v = (int)((const long long*)eidx_raw)[pos];
        else        v = ((const int*)eidx_raw)[pos];
        sIdx[ty*24 + tx] = v;
    }
    __syncthreads();

    float2 a0[6], a1[6];
    #pragma unroll
    for (int p = 0; p < 6; p++) { a0[p] = make_float2(0.f,0.f); a1[p] = make_float2(0.f,0.f); }
    int j0 = tx, j1 = tx + 96;
    #pragma unroll 8
    for (int k = 0; k < 64; k++) {
        float w0 = sW[k*192 + j0];
        float w1 = sW[k*192 + j1];
        float2 W0 = make_float2(w0, w0), W1 = make_float2(w1, w1);
        const float2* ep = (const float2*)(sEAt + k*12);
        #pragma unroll
        for (int p = 0; p < 6; p++) {
            float2 e2 = ep[p];
            ffma2(a0[p], e2, W0);
            ffma2(a1[p], e2, W1);
        }
    }
    float s0 = 0.f, q0 = 0.f, s1 = 0.f, q1 = 0.f;
    #pragma unroll
    for (int p = 0; p < 6; p++) {
        #pragma unroll
        for (int h = 0; h < 2; h++) {
            int el = 2*p + h;
            size_t d = (size_t)sIdx[ty*24 + el] * CD;
            size_t s = (size_t)sIdx[ty*24 + 12 + el] * CD;
            float u0 = (h ? a0[p].y : a0[p].x) + g_PD[d + j0] + g_PS[s + j0];
            float u1 = (h ? a1[p].y : a1[p].x) + g_PD[d + j1] + g_PS[s + j1];
            size_t eb = (size_t)(e0 + el) * CD;
            g_U[eb + j0] = u0;
            g_U[eb + j1] = u1;
            s0 += u0; q0 += u0*u0;
            s1 += u1; q1 += u1*u1;
        }
    }
    int bin = blockIdx.x & (NBINS - 1);
    atomicAdd(&g_binS[bin*CD + j0], s0);
    atomicAdd(&g_binQ[bin*CD + j0], q0);
    atomicAdd(&g_binS[bin*CD + j1], s1);
    atomicAdd(&g_binQ[bin*CD + j1], q1);
}

// ---------------- K3: reduce bins -> per-column BN scale/shift ----------
__global__ void k3_reduce(const float* __restrict__ g1, const float* __restrict__ be1,
                          const float* __restrict__ g2, const float* __restrict__ be2,
                          const float* __restrict__ g3, const float* __restrict__ be3)
{
    int j = threadIdx.x;  // 192
    double S = 0.0, Q = 0.0;
    for (int b = 0; b < NBINS; b++) { S += g_binS[b*CD + j]; Q += g_binQ[b*CD + j]; }
    double mean = S / (double)NE;
    double var  = Q / (double)NE - mean*mean;
    float g, be;
    if (j < 64)       { g = g1[j];     be = be1[j]; }
    else if (j < 128) { g = g2[j-64];  be = be2[j-64]; }
    else              { g = g3[j-128]; be = be3[j-128]; }
    float sc = g * rsqrtf((float)var + BN_EPS);
    g_scale[j] = sc;
    g_shift[j] = be - (float)mean * sc;
}

// ---------------- K4: apply BN + gate + neighbor-sum + bond_out ---------
__global__ void k4_apply(const float* __restrict__ ea, float* __restrict__ bond_out)
{
    __shared__ float smT[12][128];
    int n = blockIdx.x, j = threadIdx.x;  // 192 threads
    int e0 = n * NNBR;
    float sc = g_scale[j], sh = g_shift[j];
    #pragma unroll
    for (int el = 0; el < 12; el++) {
        float u = g_U[(size_t)(e0+el)*CD + j];
        float v = fmaf(u, sc, sh);
        if (j < 128) {
            smT[el][j] = (j < 64) ? sigmoid_f(v) : softplus_f(v);
        } else {
            int jb = j - 128;
            float eav = ea[(size_t)(e0+el)*64 + jb];
            bond_out[(size_t)(e0+el)*64 + jb] = softplus_f(eav + v);
        }
    }
    __syncthreads();
    if (j < 64) {
        float acc = 0.f;
        #pragma unroll
        for (int el = 0; el < 12; el++) acc += smT[el][j] * smT[el][j + 64];
        g_nbr[n*64 + j] = acc;
        int b = n & (NB4 - 1);
        atomicAdd(&g_b4S[b*64 + j], acc);
        atomicAdd(&g_b4Q[b*64 + j], acc*acc);
    }
}

// ---------------- K5: reduce node-BN bins ----------------
__global__ void k5_reduce(const float* __restrict__ g4, const float* __restrict__ be4)
{
    int j = threadIdx.x;  // 64
    double S = 0.0, Q = 0.0;
    for (int b = 0; b < NB4; b++) { S += g_b4S[b*64 + j]; Q += g_b4Q[b*64 + j]; }
    double mean = S / (double)NN;
    double var  = Q / (double)NN - mean*mean;
    float sc = g4[j] * rsqrtf((float)var + BN_EPS);
    g_scale4[j] = sc;
    g_shift4[j] = be4[j] - (float)mean * sc;
}

// ---------------- K6: out = softplus(x + bn4(nbr_sum)) ----------------
__global__ void k6_out(const float* __restrict__ x, float* __restrict__ out)
{
    int i = blockIdx.x * 256 + threadIdx.x;
    if (i < NN*64) {
        int j = i & 63;
        float v = x[i] + fmaf(g_nbr[i], g_scale4[j], g_shift4[j]);
        out[i] = softplus_f(v);
    }
}

extern "C" void kernel_launch(void* const* d_in, const int* in_sizes, int n_in,
                              void* d_out, int out_size)
{
    const float*     x   = (const float*)d_in[0];
    const void*      ei  = (const void*)d_in[1];
    const float*     ea  = (const float*)d_in[2];
    const float*     Wc  = (const float*)d_in[3];
    const float*     bc  = (const float*)d_in[4];
    const float*     Wf  = (const float*)d_in[5];
    const float*     bf  = (const float*)d_in[6];
    const float*     Wb  = (const float*)d_in[7];
    const float*     bb  = (const float*)d_in[8];
    const float*     g1  = (const float*)d_in[9];
    const float*     be1 = (const float*)d_in[10];
    const float*     g2  = (const float*)d_in[11];
    const float*     be2 = (const float*)d_in[12];
    const float*     g3  = (const float*)d_in[13];
    const float*     be3 = (const float*)d_in[14];
    const float*     g4  = (const float*)d_in[15];
    const float*     be4 = (const float*)d_in[16];

    float* out  = (float*)d_out;
    float* bond = out + (size_t)NN * 64;

    cudaFuncSetAttribute(k1_nodegemm, cudaFuncAttributeMaxDynamicSharedMemorySize, K1_SMEM);
    cudaFuncSetAttribute(k2_edge,     cudaFuncAttributeMaxDynamicSharedMemorySize, K2_SMEM);

    kzero<<<(NBINS*CD + 255)/256, 256>>>((const int*)ei);
    k1_nodegemm<<<NN/16, dim3(96,2,1), K1_SMEM>>>(x, Wc, bc, Wf, bf, Wb, bb);
    k2_edge<<<NN/2, dim3(96,2,1), K2_SMEM>>>(ea, ei, Wc, Wf, Wb);
    k3_reduce<<<1, 192>>>(g1, be1, g2, be2, g3, be3);
    k4_apply<<<NN, 192>>>(ea, bond);
    k5_reduce<<<1, 64>>>(g4, be4);
    k6_out<<<(NN*64 + 255)/256, 256>>>(x, out);
}

// round 3
// speedup vs baseline: 2.8925x; 2.8925x over previous
#include <cuda_runtime.h>
#include <cuda_fp16.h>
#include <math.h>

#define NN 100000
#define NNBR 12
#define NE (NN*NNBR)
#define CD 192
#define KD 64
#define NBINS 1024
#define NB4 256
#define BN_EPS 1e-5f

#define K1G 296
#define K2G 592
#define K4G 1184

// ---------------- scratch (static __device__, no allocs) ----------------
__device__ float  g_PD[(size_t)NN*CD];    // per-node dst-side partial (+bias)
__device__ float  g_PS[(size_t)NN*CD];    // per-node src-side partial
__device__ __half g_Uh[(size_t)NE*CD];    // pre-BN edge outputs (fp16, 460 MB)
__device__ float  g_binS[(size_t)CD*NBINS];  // [j][bin]
__device__ float  g_binQ[(size_t)CD*NBINS];
__device__ float  g_scale[CD];
__device__ float  g_shift[CD];
__device__ float  g_nbr[NN*KD];
__device__ float  g_b4S[KD*NB4];          // [j][bin]
__device__ float  g_b4Q[KD*NB4];
__device__ float  g_scale4[KD];
__device__ float  g_shift4[KD];
__device__ int    g_is64;                 // edge_index dtype flag

// packed f32x2 FMA: d = a*b + d
__device__ __forceinline__ void ffma2(float2 &d, float2 a, float2 b) {
    asm("fma.rn.f32x2 %0, %1, %2, %0;"
        : "+l"(reinterpret_cast<unsigned long long&>(d))
        : "l"(reinterpret_cast<unsigned long long&>(a)),
          "l"(reinterpret_cast<unsigned long long&>(b)));
}

__device__ __forceinline__ float softplus_f(float x) {
    return fmaxf(x, 0.f) + __logf(1.f + __expf(-fabsf(x)));
}
__device__ __forceinline__ float sigmoid_f(float x) {
    return __fdividef(1.f, 1.f + __expf(-x));
}

// ---------------- K0: zero stat buffers + detect index dtype --------------
__global__ void kzero(const int* __restrict__ eidx32) {
    int i = blockIdx.x * blockDim.x + threadIdx.x;
    if (i < CD*NBINS) { g_binS[i] = 0.f; g_binQ[i] = 0.f; }
    if (i < KD*NB4)   { g_b4S[i]  = 0.f; g_b4Q[i]  = 0.f; }
    if (i == 0) {
        // src = repeat(arange(N),12). int64 little-endian: word25 = hi(src[12]=1) = 0.
        // int32: word25 = src[25] = 2.
        g_is64 = (eidx32[25] == 0) ? 1 : 0;
    }
}

// ---------------- K1: node pre-GEMM  PD/PS = x @ Wparts^T (persistent) -----
#define K1_SMEM (64*384*4 + 2*64*8*4)
__global__ void k1_nodegemm(const float* __restrict__ x,
                            const float* __restrict__ Wc, const float* __restrict__ bc,
                            const float* __restrict__ Wf, const float* __restrict__ bf,
                            const float* __restrict__ Wb, const float* __restrict__ bb)
{
    extern __shared__ float sm[];
    float* sW = sm;             // [64][384]: [k][j] dst-part, [k][192+j] src-part
    float* sX = sm + 64*384;    // [2][64][8]
    int tx = threadIdx.x, ty = threadIdx.y;
    int tid = ty*96 + tx;

    for (int idx = tid; idx < 64*384; idx += 192) {
        int k  = idx / 384;
        int j3 = idx - k*384;
        int j  = (j3 >= 192) ? j3 - 192 : j3;
        int kk = (j3 >= 192) ? 64 + k : k;
        const float* W; int r;
        if (j < 64)       { W = Wc; r = j; }
        else if (j < 128) { W = Wf; r = j - 64; }
        else              { W = Wb; r = j - 128; }
        sW[idx] = W[r*CD + kk];
    }
    int j0 = tx, j1 = tx + 96;
    float bias0 = (j0 < 64) ? bc[j0] : ((j0 < 128) ? bf[j0-64] : bb[j0-128]);
    float bias1 = (j1 < 128) ? bf[j1-64] : bb[j1-128];
    float* sXt = sX + ty*512;

    for (int g = blockIdx.x; g < NN/16; g += gridDim.x) {
        int n0 = (g*2 + ty) * 8;
        __syncthreads();
        const float4* x4 = (const float4*)(x + (size_t)n0*64);
        for (int i = tx; i < 128; i += 96) {   // 8 nodes x 16 float4
            float4 v = x4[i];
            int nl = i >> 4, k4 = (i & 15) * 4;
            sXt[(k4+0)*8 + nl] = v.x;
            sXt[(k4+1)*8 + nl] = v.y;
            sXt[(k4+2)*8 + nl] = v.z;
            sXt[(k4+3)*8 + nl] = v.w;
        }
        __syncthreads();

        float2 ad0[4], ad1[4], as0[4], as1[4];
        #pragma unroll
        for (int p = 0; p < 4; p++) {
            ad0[p] = make_float2(0.f,0.f); ad1[p] = make_float2(0.f,0.f);
            as0[p] = make_float2(0.f,0.f); as1[p] = make_float2(0.f,0.f);
        }
        #pragma unroll 8
        for (int k = 0; k < 64; k++) {
            float wd0 = sW[k*384 + j0];
            float wd1 = sW[k*384 + j1];
            float ws0 = sW[k*384 + 192 + j0];
            float ws1 = sW[k*384 + 192 + j1];
            float2 Wd0 = make_float2(wd0, wd0), Wd1 = make_float2(wd1, wd1);
            float2 Ws0 = make_float2(ws0, ws0), Ws1 = make_float2(ws1, ws1);
            const float2* xp = (const float2*)(sXt + k*8);
            #pragma unroll
            for (int p = 0; p < 4; p++) {
                float2 xv = xp[p];
                ffma2(ad0[p], xv, Wd0);
                ffma2(ad1[p], xv, Wd1);
                ffma2(as0[p], xv, Ws0);
                ffma2(as1[p], xv, Ws1);
            }
        }
        #pragma unroll
        for (int p = 0; p < 4; p++) {
            size_t na = (size_t)(n0 + 2*p)*CD, nb = na + CD;
            g_PD[na + j0] = ad0[p].x + bias0;
            g_PD[nb + j0] = ad0[p].y + bias0;
            g_PD[na + j1] = ad1[p].x + bias1;
            g_PD[nb + j1] = ad1[p].y + bias1;
            g_PS[na + j0] = as0[p].x;
            g_PS[nb + j0] = as0[p].y;
            g_PS[na + j1] = as1[p].x;
            g_PS[nb + j1] = as1[p].y;
        }
    }
}

// ---------------- K2: edge GEMM + gathers -> Uh, stats (persistent) --------
#define K2_SMEM (64*192*4 + 2*64*12*4 + 2*12*4)
__global__ void k2_edge(const float* __restrict__ ea,
                        const void* __restrict__ eidx_raw,
                        const float* __restrict__ Wc,
                        const float* __restrict__ Wf,
                        const float* __restrict__ Wb)
{
    extern __shared__ float sm[];
    float* sW  = sm;                       // [64][192] edge-part of W, [k][j]
    float* sEA = sm + 64*192;              // [2][64][12]
    int*  sIdx = (int*)(sEA + 2*64*12);    // [2][12] dst indices
    int tx = threadIdx.x, ty = threadIdx.y;
    int tid = ty*96 + tx;

    for (int idx = tid; idx < 64*192; idx += 192) {
        int k = idx / 192;
        int j = idx - k*192;
        const float* W; int r;
        if (j < 64)       { W = Wc; r = j; }
        else if (j < 128) { W = Wf; r = j - 64; }
        else              { W = Wb; r = j - 128; }
        sW[idx] = W[r*CD + 128 + k];
    }
    int is64 = g_is64;
    int j0 = tx, j1 = tx + 96;
    float* sEAt = sEA + ty*768;
    float s0 = 0.f, q0 = 0.f, s1 = 0.f, q1 = 0.f;

    for (int g = blockIdx.x; g < NN/2; g += gridDim.x) {
        int n  = g*2 + ty;
        int e0 = n * NNBR;
        __syncthreads();
        const float4* ea4 = (const float4*)(ea + (size_t)e0*64);
        for (int i = tx; i < 192; i += 96) {   // 12 edges x 16 float4
            float4 v = ea4[i];
            int el = i >> 4, k4 = (i & 15) * 4;
            sEAt[(k4+0)*12 + el] = v.x;
            sEAt[(k4+1)*12 + el] = v.y;
            sEAt[(k4+2)*12 + el] = v.z;
            sEAt[(k4+3)*12 + el] = v.w;
        }
        if (tx < 12) {
            size_t pos = (size_t)NE + e0 + tx;   // dst half of edge_index
            int v;
            if (is64) v = (int)((const long long*)eidx_raw)[pos];
            else      v = ((const int*)eidx_raw)[pos];
            sIdx[ty*12 + tx] = v;
        }
        __syncthreads();

        float2 a0[6], a1[6];
        #pragma unroll
        for (int p = 0; p < 6; p++) { a0[p] = make_float2(0.f,0.f); a1[p] = make_float2(0.f,0.f); }
        #pragma unroll 8
        for (int k = 0; k < 64; k++) {
            float w0 = sW[k*192 + j0];
            float w1 = sW[k*192 + j1];
            float2 W0 = make_float2(w0, w0), W1 = make_float2(w1, w1);
            const float2* ep = (const float2*)(sEAt + k*12);
            #pragma unroll
            for (int p = 0; p < 6; p++) {
                float2 e2 = ep[p];
                ffma2(a0[p], e2, W0);
                ffma2(a1[p], e2, W1);
            }
        }
        // src row is the node itself (src = repeat(arange(N),12)) — load once
        float ps0 = g_PS[(size_t)n*CD + j0];
        float ps1 = g_PS[(size_t)n*CD + j1];
        #pragma unroll
        for (int p = 0; p < 6; p++) {
            #pragma unroll
            for (int h = 0; h < 2; h++) {
                int el = 2*p + h;
                size_t d = (size_t)sIdx[ty*12 + el] * CD;
                float u0 = (h ? a0[p].y : a0[p].x) + g_PD[d + j0] + ps0;
                float u1 = (h ? a1[p].y : a1[p].x) + g_PD[d + j1] + ps1;
                size_t eb = (size_t)(e0 + el) * CD;
                g_Uh[eb + j0] = __float2half_rn(u0);
                g_Uh[eb + j1] = __float2half_rn(u1);
                s0 += u0; q0 += u0*u0;
                s1 += u1; q1 += u1*u1;
            }
        }
    }
    int bin = blockIdx.x & (NBINS - 1);
    atomicAdd(&g_binS[(size_t)j0*NBINS + bin], s0);
    atomicAdd(&g_binQ[(size_t)j0*NBINS + bin], q0);
    atomicAdd(&g_binS[(size_t)j1*NBINS + bin], s1);
    atomicAdd(&g_binQ[(size_t)j1*NBINS + bin], q1);
}

// ---------------- K3: parallel reduce -> edge-BN scale/shift ----------
__global__ void k3_reduce(const float* __restrict__ g1, const float* __restrict__ be1,
                          const float* __restrict__ g2, const float* __restrict__ be2,
                          const float* __restrict__ g3, const float* __restrict__ be3)
{
    __shared__ float sS[256], sQ[256];
    int j = blockIdx.x, t = threadIdx.x;
    float S = 0.f, Q = 0.f;
    for (int b = t; b < NBINS; b += 256) {
        S += g_binS[(size_t)j*NBINS + b];
        Q += g_binQ[(size_t)j*NBINS + b];
    }
    sS[t] = S; sQ[t] = Q;
    __syncthreads();
    for (int o = 128; o > 0; o >>= 1) {
        if (t < o) { sS[t] += sS[t+o]; sQ[t] += sQ[t+o]; }
        __syncthreads();
    }
    if (t == 0) {
        float mean = sS[0] / (float)NE;
        float var  = sQ[0] / (float)NE - mean*mean;
        float g, be;
        if (j < 64)       { g = g1[j];     be = be1[j]; }
        else if (j < 128) { g = g2[j-64];  be = be2[j-64]; }
        else              { g = g3[j-128]; be = be3[j-128]; }
        float sc = g * rsqrtf(var + BN_EPS);
        g_scale[j] = sc;
        g_shift[j] = be - mean * sc;
    }
}

// ---------------- K4: BN + gate + neighbor-sum + bond_out (persistent) -----
__global__ void k4_apply(const float* __restrict__ ea, float* __restrict__ bond_out)
{
    __shared__ float smT[12][128];
    int j = threadIdx.x;  // 192
    float sc = g_scale[j], sh = g_shift[j];
    float sS = 0.f, sQ = 0.f;
    for (int n = blockIdx.x; n < NN; n += gridDim.x) {
        int e0 = n * NNBR;
        __syncthreads();
        if (j < 128) {
            #pragma unroll
            for (int el = 0; el < 12; el++) {
                float u = __half2float(g_Uh[(size_t)(e0+el)*CD + j]);
                float v = fmaf(u, sc, sh);
                smT[el][j] = (j < 64) ? sigmoid_f(v) : softplus_f(v);
            }
        } else {
            int jb = j - 128;
            #pragma unroll
            for (int el = 0; el < 12; el++) {
                float u = __half2float(g_Uh[(size_t)(e0+el)*CD + j]);
                float v = fmaf(u, sc, sh);
                float eav = ea[(size_t)(e0+el)*64 + jb];
                bond_out[(size_t)(e0+el)*64 + jb] = softplus_f(eav + v);
            }
        }
        __syncthreads();
        if (j < 64) {
            float acc = 0.f;
            #pragma unroll
            for (int el = 0; el < 12; el++) acc += smT[el][j] * smT[el][j + 64];
            g_nbr[n*64 + j] = acc;
            sS += acc; sQ += acc*acc;
        }
    }
    if (j < 64) {
        int b = blockIdx.x & (NB4 - 1);
        atomicAdd(&g_b4S[j*NB4 + b], sS);
        atomicAdd(&g_b4Q[j*NB4 + b], sQ);
    }
}

// ---------------- K5: parallel reduce node-BN ----------------
__global__ void k5_reduce(const float* __restrict__ g4, const float* __restrict__ be4)
{
    __shared__ float sS[256], sQ[256];
    int j = blockIdx.x, t = threadIdx.x;
    float S = (t < NB4) ? g_b4S[j*NB4 + t] : 0.f;
    float Q = (t < NB4) ? g_b4Q[j*NB4 + t] : 0.f;
    sS[t] = S; sQ[t] = Q;
    __syncthreads();
    for (int o = 128; o > 0; o >>= 1) {
        if (t < o) { sS[t] += sS[t+o]; sQ[t] += sQ[t+o]; }
        __syncthreads();
    }
    if (t == 0) {
        float mean = sS[0] / (float)NN;
        float var  = sQ[0] / (float)NN - mean*mean;
        float sc = g4[j] * rsqrtf(var + BN_EPS);
        g_scale4[j] = sc;
        g_shift4[j] = be4[j] - mean * sc;
    }
}

// ---------------- K6: out = softplus(x + bn4(nbr_sum)) ----------------
__global__ void k6_out(const float* __restrict__ x, float* __restrict__ out)
{
    int i = blockIdx.x * 256 + threadIdx.x;
    if (i < NN*64) {
        int j = i & 63;
        float v = x[i] + fmaf(g_nbr[i], g_scale4[j], g_shift4[j]);
        out[i] = softplus_f(v);
    }
}

extern "C" void kernel_launch(void* const* d_in, const int* in_sizes, int n_in,
                              void* d_out, int out_size)
{
    const float* x   = (const float*)d_in[0];
    const void*  ei  = (const void*)d_in[1];
    const float* ea  = (const float*)d_in[2];
    const float* Wc  = (const float*)d_in[3];
    const float* bc  = (const float*)d_in[4];
    const float* Wf  = (const float*)d_in[5];
    const float* bf  = (const float*)d_in[6];
    const float* Wb  = (const float*)d_in[7];
    const float* bb  = (const float*)d_in[8];
    const float* g1  = (const float*)d_in[9];
    const float* be1 = (const float*)d_in[10];
    const float* g2  = (const float*)d_in[11];
    const float* be2 = (const float*)d_in[12];
    const float* g3  = (const float*)d_in[13];
    const float* be3 = (const float*)d_in[14];
    const float* g4  = (const float*)d_in[15];
    const float* be4 = (const float*)d_in[16];

    float* out  = (float*)d_out;
    float* bond = out + (size_t)NN * 64;

    cudaFuncSetAttribute(k1_nodegemm, cudaFuncAttributeMaxDynamicSharedMemorySize, K1_SMEM);
    cudaFuncSetAttribute(k2_edge,     cudaFuncAttributeMaxDynamicSharedMemorySize, K2_SMEM);

    kzero<<<(CD*NBINS + 255)/256, 256>>>((const int*)ei);
    k1_nodegemm<<<K1G, dim3(96,2,1), K1_SMEM>>>(x, Wc, bc, Wf, bf, Wb, bb);
    k2_edge<<<K2G, dim3(96,2,1), K2_SMEM>>>(ea, ei, Wc, Wf, Wb);
    k3_reduce<<<CD, 256>>>(g1, be1, g2, be2, g3, be3);
    k4_apply<<<K4G, 192>>>(ea, bond);
    k5_reduce<<<KD, 256>>>(g4, be4);
    k6_out<<<(NN*64 + 255)/256, 256>>>(x, out);
}

// round 4
// speedup vs baseline: 3.8272x; 1.3232x over previous
#include <cuda_runtime.h>
#include <cuda_fp16.h>
#include <math.h>

#define NN 100000
#define NNBR 12
#define NE (NN*NNBR)
#define CD 192
#define KD 64
#define NBINS 1024
#define NB4 256
#define BN_EPS 1e-5f

#define K1G 296
#define K2G 296
#define K4G 1184

// ---------------- scratch (static __device__, no allocs) ----------------
__device__ __half g_PDh[(size_t)NN*CD];   // per-node dst-side partial (+bias), fp16
__device__ __half g_PSh[(size_t)NN*CD];   // per-node src-side partial, fp16
__device__ __half g_Uh[(size_t)NE*CD];    // pre-BN edge outputs (fp16, 460 MB)
__device__ float  g_binS[(size_t)CD*NBINS];  // [j][bin]
__device__ float  g_binQ[(size_t)CD*NBINS];
__device__ float  g_scale[CD];
__device__ float  g_shift[CD];
__device__ float  g_nbr[NN*KD];
__device__ float  g_b4S[KD*NB4];          // [j][bin]
__device__ float  g_b4Q[KD*NB4];
__device__ float  g_scale4[KD];
__device__ float  g_shift4[KD];
__device__ int    g_is64;                 // edge_index dtype flag

// packed f32x2 FMA: d = a*b + d
__device__ __forceinline__ void ffma2(float2 &d, float2 a, float2 b) {
    asm("fma.rn.f32x2 %0, %1, %2, %0;"
        : "+l"(reinterpret_cast<unsigned long long&>(d))
        : "l"(reinterpret_cast<unsigned long long&>(a)),
          "l"(reinterpret_cast<unsigned long long&>(b)));
}

__device__ __forceinline__ void mma16816(float* c, const unsigned* a, const unsigned* b) {
    asm volatile(
        "mma.sync.aligned.m16n8k16.row.col.f32.f16.f16.f32 "
        "{%0,%1,%2,%3}, {%4,%5,%6,%7}, {%8,%9}, {%0,%1,%2,%3};"
        : "+f"(c[0]), "+f"(c[1]), "+f"(c[2]), "+f"(c[3])
        : "r"(a[0]), "r"(a[1]), "r"(a[2]), "r"(a[3]), "r"(b[0]), "r"(b[1]));
}

__device__ __forceinline__ float softplus_f(float x) {
    return fmaxf(x, 0.f) + __logf(1.f + __expf(-fabsf(x)));
}
__device__ __forceinline__ float sigmoid_f(float x) {
    return __fdividef(1.f, 1.f + __expf(-x));
}

// ---------------- K0: zero stat buffers + detect index dtype --------------
__global__ void kzero(const int* __restrict__ eidx32) {
    int i = blockIdx.x * blockDim.x + threadIdx.x;
    if (i < CD*NBINS) { g_binS[i] = 0.f; g_binQ[i] = 0.f; }
    if (i < KD*NB4)   { g_b4S[i]  = 0.f; g_b4Q[i]  = 0.f; }
    if (i == 0) {
        // src = repeat(arange(N),12). int64 LE: word25 = hi(src[12]=1) = 0. int32: word25 = 2.
        g_is64 = (eidx32[25] == 0) ? 1 : 0;
    }
}

// ---------------- K1: node pre-GEMM  PD/PS = x @ Wparts^T (persistent) -----
#define K1_SMEM (64*384*4 + 2*64*8*4)
__global__ void k1_nodegemm(const float* __restrict__ x,
                            const float* __restrict__ Wc, const float* __restrict__ bc,
                            const float* __restrict__ Wf, const float* __restrict__ bf,
                            const float* __restrict__ Wb, const float* __restrict__ bb)
{
    extern __shared__ float sm[];
    float* sW = sm;             // [64][384]: [k][j] dst-part, [k][192+j] src-part
    float* sX = sm + 64*384;    // [2][64][8]
    int tx = threadIdx.x, ty = threadIdx.y;
    int tid = ty*96 + tx;

    for (int idx = tid; idx < 64*384; idx += 192) {
        int k  = idx / 384;
        int j3 = idx - k*384;
        int j  = (j3 >= 192) ? j3 - 192 : j3;
        int kk = (j3 >= 192) ? 64 + k : k;
        const float* W; int r;
        if (j < 64)       { W = Wc; r = j; }
        else if (j < 128) { W = Wf; r = j - 64; }
        else              { W = Wb; r = j - 128; }
        sW[idx] = W[r*CD + kk];
    }
    int j0 = tx, j1 = tx + 96;
    float bias0 = (j0 < 64) ? bc[j0] : ((j0 < 128) ? bf[j0-64] : bb[j0-128]);
    float bias1 = (j1 < 128) ? bf[j1-64] : bb[j1-128];
    float* sXt = sX + ty*512;

    for (int g = blockIdx.x; g < NN/16; g += gridDim.x) {
        int n0 = (g*2 + ty) * 8;
        __syncthreads();
        const float4* x4 = (const float4*)(x + (size_t)n0*64);
        for (int i = tx; i < 128; i += 96) {
            float4 v = x4[i];
            int nl = i >> 4, k4 = (i & 15) * 4;
            sXt[(k4+0)*8 + nl] = v.x;
            sXt[(k4+1)*8 + nl] = v.y;
            sXt[(k4+2)*8 + nl] = v.z;
            sXt[(k4+3)*8 + nl] = v.w;
        }
        __syncthreads();

        float2 ad0[4], ad1[4], as0[4], as1[4];
        #pragma unroll
        for (int p = 0; p < 4; p++) {
            ad0[p] = make_float2(0.f,0.f); ad1[p] = make_float2(0.f,0.f);
            as0[p] = make_float2(0.f,0.f); as1[p] = make_float2(0.f,0.f);
        }
        #pragma unroll 8
        for (int k = 0; k < 64; k++) {
            float wd0 = sW[k*384 + j0];
            float wd1 = sW[k*384 + j1];
            float ws0 = sW[k*384 + 192 + j0];
            float ws1 = sW[k*384 + 192 + j1];
            float2 Wd0 = make_float2(wd0, wd0), Wd1 = make_float2(wd1, wd1);
            float2 Ws0 = make_float2(ws0, ws0), Ws1 = make_float2(ws1, ws1);
            const float2* xp = (const float2*)(sXt + k*8);
            #pragma unroll
            for (int p = 0; p < 4; p++) {
                float2 xv = xp[p];
                ffma2(ad0[p], xv, Wd0);
                ffma2(ad1[p], xv, Wd1);
                ffma2(as0[p], xv, Ws0);
                ffma2(as1[p], xv, Ws1);
            }
        }
        #pragma unroll
        for (int p = 0; p < 4; p++) {
            size_t na = (size_t)(n0 + 2*p)*CD, nb = na + CD;
            g_PDh[na + j0] = __float2half_rn(ad0[p].x + bias0);
            g_PDh[nb + j0] = __float2half_rn(ad0[p].y + bias0);
            g_PDh[na + j1] = __float2half_rn(ad1[p].x + bias1);
            g_PDh[nb + j1] = __float2half_rn(ad1[p].y + bias1);
            g_PSh[na + j0] = __float2half_rn(as0[p].x);
            g_PSh[nb + j0] = __float2half_rn(as0[p].y);
            g_PSh[na + j1] = __float2half_rn(as1[p].x);
            g_PSh[nb + j1] = __float2half_rn(as1[p].y);
        }
    }
}

// ---------------- K2: edge GEMM via HMMA (persistent) ----------------------
// Tile: M=32 edges, N=192, K=64. 8 warps = 2(m) x 4(n); warp = m16 x n48.
// B (W_edge) fragments live in registers for the whole kernel.
#define SEA_U32  (32*36)          // ea tile fp16, stride 72 halves (36 u32)
#define SPD_F32  (32*200)         // PD+PS pre-summed fp32, stride 200 floats
#define SW_U32   (192*32)         // W_edge fp16 [n][64k] as u32
#define K2_SMEM  ((SW_U32 + SEA_U32)*4 + SPD_F32*4)
__global__ void __launch_bounds__(256, 2)
k2_edge(const float* __restrict__ ea,
        const void* __restrict__ eidx_raw,
        const float* __restrict__ Wc,
        const float* __restrict__ Wf,
        const float* __restrict__ Wb)
{
    extern __shared__ unsigned smu[];
    unsigned* sW32  = smu;                    // [192][32] u32 (=64 halves/row)
    unsigned* sEA32 = smu + SW_U32;           // [32][36] u32 (72 halves/row)
    float*    sPD   = (float*)(smu + SW_U32 + SEA_U32);  // [32][200]
    int tid = threadIdx.x;
    int w   = tid >> 5, lane = tid & 31;
    int gq  = lane >> 2, tl = lane & 3;       // quad row / col-pair ids
    int mb  = (w & 1) * 16;                   // warp m offset
    int nb  = (w >> 1) * 48;                  // warp n offset
    int is64 = g_is64;

    // Stage W_edge -> smem fp16 [n][k]
    for (int i = tid; i < 192*32; i += 256) {
        int n = i >> 5, k2 = i & 31;
        const float* W; int r;
        if (n < 64)       { W = Wc; r = n; }
        else if (n < 128) { W = Wf; r = n - 64; }
        else              { W = Wb; r = n - 128; }
        float2 v = *(const float2*)(W + (size_t)r*CD + 128 + 2*k2);
        __half2 h = __floats2half2_rn(v.x, v.y);
        sW32[n*32 + k2] = *(unsigned*)&h;
    }
    __syncthreads();

    // B fragments: [nt][ks][2], persistent in registers
    unsigned Bf[6][4][2];
    #pragma unroll
    for (int nt = 0; nt < 6; nt++) {
        int n = nb + nt*8 + gq;
        #pragma unroll
        for (int ks = 0; ks < 4; ks++) {
            Bf[nt][ks][0] = sW32[n*32 + ks*8 + tl];
            Bf[nt][ks][1] = sW32[n*32 + ks*8 + tl + 4];
        }
    }
    __syncthreads();

    // per-lane stats: cols nb + nt*8 + 2*tl (+1), fixed across iterations
    float sS[12], sQ[12];
    #pragma unroll
    for (int i = 0; i < 12; i++) { sS[i] = 0.f; sQ[i] = 0.f; }

    const int NT = NE / 32;   // 37500
    for (int tile = blockIdx.x; tile < NT; tile += gridDim.x) {
        int ebase = tile * 32;

        // ---- stage ea tile (fp32 -> fp16) ----
        #pragma unroll
        for (int i = 0; i < 4; i++) {
            int f = tid + i*256;              // 0..1023
            int r = f >> 5, c2 = f & 31;
            float2 v = *(const float2*)(ea + (size_t)(ebase+r)*64 + 2*c2);
            __half2 h = __floats2half2_rn(v.x, v.y);
            sEA32[r*36 + c2] = *(unsigned*)&h;
        }
        // ---- stage PD[dst]+PS[src] rows (fp16 gather -> fp32 sum) ----
        #pragma unroll
        for (int i = 0; i < 12; i++) {
            int f = tid + i*256;              // 0..3071
            int r = f / 96, c2 = f - r*96;
            int e = ebase + r;
            int dst;
            if (is64) dst = (int)((const long long*)eidx_raw)[(size_t)NE + e];
            else      dst = ((const int*)eidx_raw)[(size_t)NE + e];
            int src = e / 12;
            __half2 pd = *(const __half2*)(g_PDh + (size_t)dst*CD + 2*c2);
            __half2 ps = *(const __half2*)(g_PSh + (size_t)src*CD + 2*c2);
            float2 a = __half22float2(pd), b = __half22float2(ps);
            sPD[r*200 + 2*c2]     = a.x + b.x;
            sPD[r*200 + 2*c2 + 1] = a.y + b.y;
        }
        __syncthreads();

        // ---- mma mainloop ----
        float C[6][4];
        #pragma unroll
        for (int nt = 0; nt < 6; nt++)
            #pragma unroll
            for (int q = 0; q < 4; q++) C[nt][q] = 0.f;

        #pragma unroll
        for (int ks = 0; ks < 4; ks++) {
            unsigned A[4];
            A[0] = sEA32[(mb+gq)*36   + ks*8 + tl];
            A[1] = sEA32[(mb+gq+8)*36 + ks*8 + tl];
            A[2] = sEA32[(mb+gq)*36   + ks*8 + tl + 4];
            A[3] = sEA32[(mb+gq+8)*36 + ks*8 + tl + 4];
            #pragma unroll
            for (int nt = 0; nt < 6; nt++)
                mma16816(C[nt], A, Bf[nt][ks]);
        }

        // ---- epilogue: add PD+PS, store fp16 U, accumulate stats ----
        int r0 = mb + gq, r1 = r0 + 8;
        size_t e0 = (size_t)(ebase + r0) * CD;
        size_t e1 = (size_t)(ebase + r1) * CD;
        #pragma unroll
        for (int nt = 0; nt < 6; nt++) {
            int col = nb + nt*8 + 2*tl;
            float2 p0 = *(const float2*)(sPD + r0*200 + col);
            float2 p1 = *(const float2*)(sPD + r1*200 + col);
            float u0x = C[nt][0] + p0.x, u0y = C[nt][1] + p0.y;
            float u1x = C[nt][2] + p1.x, u1y = C[nt][3] + p1.y;
            __half2 h0 = __floats2half2_rn(u0x, u0y);
            __half2 h1 = __floats2half2_rn(u1x, u1y);
            *(__half2*)(g_Uh + e0 + col) = h0;
            *(__half2*)(g_Uh + e1 + col) = h1;
            sS[nt*2]   += u0x + u1x;
            sQ[nt*2]   += u0x*u0x + u1x*u1x;
            sS[nt*2+1] += u0y + u1y;
            sQ[nt*2+1] += u0y*u0y + u1y*u1y;
        }
        __syncthreads();
    }

    // reduce stats over the 8 g-lanes sharing the same cols, then atomics
    #pragma unroll
    for (int i = 0; i < 12; i++) {
        sS[i] += __shfl_xor_sync(0xffffffff, sS[i], 4);
        sS[i] += __shfl_xor_sync(0xffffffff, sS[i], 8);
        sS[i] += __shfl_xor_sync(0xffffffff, sS[i], 16);
        sQ[i] += __shfl_xor_sync(0xffffffff, sQ[i], 4);
        sQ[i] += __shfl_xor_sync(0xffffffff, sQ[i], 8);
        sQ[i] += __shfl_xor_sync(0xffffffff, sQ[i], 16);
    }
    if (lane < 4) {
        int bin = blockIdx.x & (NBINS - 1);
        #pragma unroll
        for (int nt = 0; nt < 6; nt++) {
            int col = nb + nt*8 + 2*lane;
            atomicAdd(&g_binS[(size_t)col*NBINS + bin],     sS[nt*2]);
            atomicAdd(&g_binQ[(size_t)col*NBINS + bin],     sQ[nt*2]);
            atomicAdd(&g_binS[(size_t)(col+1)*NBINS + bin], sS[nt*2+1]);
            atomicAdd(&g_binQ[(size_t)(col+1)*NBINS + bin], sQ[nt*2+1]);
        }
    }
}

// ---------------- K3: parallel reduce -> edge-BN scale/shift ----------
__global__ void k3_reduce(const float* __restrict__ g1, const float* __restrict__ be1,
                          const float* __restrict__ g2, const float* __restrict__ be2,
                          const float* __restrict__ g3, const float* __restrict__ be3)
{
    __shared__ float sS[256], sQ[256];
    int j = blockIdx.x, t = threadIdx.x;
    float S = 0.f, Q = 0.f;
    for (int b = t; b < NBINS; b += 256) {
        S += g_binS[(size_t)j*NBINS + b];
        Q += g_binQ[(size_t)j*NBINS + b];
    }
    sS[t] = S; sQ[t] = Q;
    __syncthreads();
    for (int o = 128; o > 0; o >>= 1) {
        if (t < o) { sS[t] += sS[t+o]; sQ[t] += sQ[t+o]; }
        __syncthreads();
    }
    if (t == 0) {
        float mean = sS[0] / (float)NE;
        float var  = sQ[0] / (float)NE - mean*mean;
        float g, be;
        if (j < 64)       { g = g1[j];     be = be1[j]; }
        else if (j < 128) { g = g2[j-64];  be = be2[j-64]; }
        else              { g = g3[j-128]; be = be3[j-128]; }
        float sc = g * rsqrtf(var + BN_EPS);
        g_scale[j] = sc;
        g_shift[j] = be - mean * sc;
    }
}

// ---------------- K4: BN + gate + neighbor-sum + bond_out (persistent) -----
__global__ void k4_apply(const float* __restrict__ ea, float* __restrict__ bond_out)
{
    __shared__ float smT[12][128];
    int j = threadIdx.x;  // 192
    float sc = g_scale[j], sh = g_shift[j];
    float sS = 0.f, sQ = 0.f;
    for (int n = blockIdx.x; n < NN; n += gridDim.x) {
        int e0 = n * NNBR;
        __syncthreads();
        if (j < 128) {
            #pragma unroll
            for (int el = 0; el < 12; el++) {
                float u = __half2float(g_Uh[(size_t)(e0+el)*CD + j]);
                float v = fmaf(u, sc, sh);
                smT[el][j] = (j < 64) ? sigmoid_f(v) : softplus_f(v);
            }
        } else {
            int jb = j - 128;
            #pragma unroll
            for (int el = 0; el < 12; el++) {
                float u = __half2float(g_Uh[(size_t)(e0+el)*CD + j]);
                float v = fmaf(u, sc, sh);
                float eav = ea[(size_t)(e0+el)*64 + jb];
                bond_out[(size_t)(e0+el)*64 + jb] = softplus_f(eav + v);
            }
        }
        __syncthreads();
        if (j < 64) {
            float acc = 0.f;
            #pragma unroll
            for (int el = 0; el < 12; el++) acc += smT[el][j] * smT[el][j + 64];
            g_nbr[n*64 + j] = acc;
            sS += acc; sQ += acc*acc;
        }
    }
    if (j < 64) {
        int b = blockIdx.x & (NB4 - 1);
        atomicAdd(&g_b4S[j*NB4 + b], sS);
        atomicAdd(&g_b4Q[j*NB4 + b], sQ);
    }
}

// ---------------- K5: parallel reduce node-BN ----------------
__global__ void k5_reduce(const float* __restrict__ g4, const float* __restrict__ be4)
{
    __shared__ float sS[256], sQ[256];
    int j = blockIdx.x, t = threadIdx.x;
    float S = (t < NB4) ? g_b4S[j*NB4 + t] : 0.f;
    float Q = (t < NB4) ? g_b4Q[j*NB4 + t] : 0.f;
    sS[t] = S; sQ[t] = Q;
    __syncthreads();
    for (int o = 128; o > 0; o >>= 1) {
        if (t < o) { sS[t] += sS[t+o]; sQ[t] += sQ[t+o]; }
        __syncthreads();
    }
    if (t == 0) {
        float mean = sS[0] / (float)NN;
        float var  = sQ[0] / (float)NN - mean*mean;
        float sc = g4[j] * rsqrtf(var + BN_EPS);
        g_scale4[j] = sc;
        g_shift4[j] = be4[j] - mean * sc;
    }
}

// ---------------- K6: out = softplus(x + bn4(nbr_sum)) ----------------
__global__ void k6_out(const float* __restrict__ x, float* __restrict__ out)
{
    int i = blockIdx.x * 256 + threadIdx.x;
    if (i < NN*64) {
        int j = i & 63;
        float v = x[i] + fmaf(g_nbr[i], g_scale4[j], g_shift4[j]);
        out[i] = softplus_f(v);
    }
}

extern "C" void kernel_launch(void* const* d_in, const int* in_sizes, int n_in,
                              void* d_out, int out_size)
{
    const float* x   = (const float*)d_in[0];
    const void*  ei  = (const void*)d_in[1];
    const float* ea  = (const float*)d_in[2];
    const float* Wc  = (const float*)d_in[3];
    const float* bc  = (const float*)d_in[4];
    const float* Wf  = (const float*)d_in[5];
    const float* bf  = (const float*)d_in[6];
    const float* Wb  = (const float*)d_in[7];
    const float* bb  = (const float*)d_in[8];
    const float* g1  = (const float*)d_in[9];
    const float* be1 = (const float*)d_in[10];
    const float* g2  = (const float*)d_in[11];
    const float* be2 = (const float*)d_in[12];
    const float* g3  = (const float*)d_in[13];
    const float* be3 = (const float*)d_in[14];
    const float* g4  = (const float*)d_in[15];
    const float* be4 = (const float*)d_in[16];

    float* out  = (float*)d_out;
    float* bond = out + (size_t)NN * 64;

    cudaFuncSetAttribute(k1_nodegemm, cudaFuncAttributeMaxDynamicSharedMemorySize, K1_SMEM);
    cudaFuncSetAttribute(k2_edge,     cudaFuncAttributeMaxDynamicSharedMemorySize, K2_SMEM);

    kzero<<<(CD*NBINS + 255)/256, 256>>>((const int*)ei);
    k1_nodegemm<<<K1G, dim3(96,2,1), K1_SMEM>>>(x, Wc, bc, Wf, bf, Wb, bb);
    k2_edge<<<K2G, 256, K2_SMEM>>>(ea, ei, Wc, Wf, Wb);
    k3_reduce<<<CD, 256>>>(g1, be1, g2, be2, g3, be3);
    k4_apply<<<K4G, 192>>>(ea, bond);
    k5_reduce<<<KD, 256>>>(g4, be4);
    k6_out<<<(NN*64 + 255)/256, 256>>>(x, out);
}

// round 5
// speedup vs baseline: 6.7516x; 1.7641x over previous
#include <cuda_runtime.h>
#include <cuda_fp16.h>
#include <math.h>

#define NN 100000
#define NNBR 12
#define NE (NN*NNBR)
#define CD 192
#define KD 64
#define NBINS 1024
#define NB4 256
#define BN_EPS 1e-5f

#define K1G 296
#define K2G 296
#define K4G 592

// ---------------- scratch (static __device__, no allocs) ----------------
__device__ __half g_PDh[(size_t)NN*CD];   // per-node dst-side partial (+bias), fp16
__device__ __half g_PSh[(size_t)NN*CD];   // per-node src-side partial, fp16
__device__ __half g_Uh[(size_t)NE*CD];    // pre-BN edge outputs (fp16, 460 MB)
__device__ float  g_binS[(size_t)CD*NBINS];  // [j][bin]
__device__ float  g_binQ[(size_t)CD*NBINS];
__device__ float  g_scale[CD];
__device__ float  g_shift[CD];
__device__ float  g_nbr[NN*KD];
__device__ float  g_b4S[KD*NB4];          // [j][bin]
__device__ float  g_b4Q[KD*NB4];
__device__ float  g_scale4[KD];
__device__ float  g_shift4[KD];
__device__ int    g_is64;                 // edge_index dtype flag

// packed f32x2 FMA: d = a*b + d
__device__ __forceinline__ void ffma2(float2 &d, float2 a, float2 b) {
    asm("fma.rn.f32x2 %0, %1, %2, %0;"
        : "+l"(reinterpret_cast<unsigned long long&>(d))
        : "l"(reinterpret_cast<unsigned long long&>(a)),
          "l"(reinterpret_cast<unsigned long long&>(b)));
}

__device__ __forceinline__ void mma16816(float* c, const unsigned* a, const unsigned* b) {
    asm volatile(
        "mma.sync.aligned.m16n8k16.row.col.f32.f16.f16.f32 "
        "{%0,%1,%2,%3}, {%4,%5,%6,%7}, {%8,%9}, {%0,%1,%2,%3};"
        : "+f"(c[0]), "+f"(c[1]), "+f"(c[2]), "+f"(c[3])
        : "r"(a[0]), "r"(a[1]), "r"(a[2]), "r"(a[3]), "r"(b[0]), "r"(b[1]));
}

__device__ __forceinline__ unsigned smem_u32(const void* p) {
    return (unsigned)__cvta_generic_to_shared(p);
}
__device__ __forceinline__ void cpa16(unsigned s, const void* g) {
    asm volatile("cp.async.cg.shared.global [%0], [%1], 16;" :: "r"(s), "l"(g));
}
__device__ __forceinline__ void cpa_commit() {
    asm volatile("cp.async.commit_group;");
}
__device__ __forceinline__ void cpa_wait1() {
    asm volatile("cp.async.wait_group 1;");
}

__device__ __forceinline__ float softplus_f(float x) {
    return fmaxf(x, 0.f) + __logf(1.f + __expf(-fabsf(x)));
}
__device__ __forceinline__ float sigmoid_f(float x) {
    return __fdividef(1.f, 1.f + __expf(-x));
}

// ---------------- K1: zero stats + detect dtype + node pre-GEMM -----------
#define K1_SMEM (64*384*4 + 2*64*8*4)
__global__ void k1_nodegemm(const float* __restrict__ x,
                            const int*   __restrict__ eidx32,
                            const float* __restrict__ Wc, const float* __restrict__ bc,
                            const float* __restrict__ Wf, const float* __restrict__ bf,
                            const float* __restrict__ Wb, const float* __restrict__ bb)
{
    extern __shared__ float sm[];
    float* sW = sm;             // [64][384]: [k][j] dst-part, [k][192+j] src-part
    float* sX = sm + 64*384;    // [2][64][8]
    int tx = threadIdx.x, ty = threadIdx.y;
    int tid = ty*96 + tx;
    int gtid = blockIdx.x*192 + tid;

    // zero stat bins (done before k2/k4 run; stream-ordered)
    for (int i = gtid; i < CD*NBINS; i += K1G*192) { g_binS[i] = 0.f; g_binQ[i] = 0.f; }
    for (int i = gtid; i < KD*NB4;   i += K1G*192) { g_b4S[i]  = 0.f; g_b4Q[i]  = 0.f; }
    if (gtid == 0) {
        // src = repeat(arange(N),12). int64 LE: word25 = hi(src[12]=1) = 0. int32: word25 = 2.
        g_is64 = (eidx32[25] == 0) ? 1 : 0;
    }

    for (int idx = tid; idx < 64*384; idx += 192) {
        int k  = idx / 384;
        int j3 = idx - k*384;
        int j  = (j3 >= 192) ? j3 - 192 : j3;
        int kk = (j3 >= 192) ? 64 + k : k;
        const float* W; int r;
        if (j < 64)       { W = Wc; r = j; }
        else if (j < 128) { W = Wf; r = j - 64; }
        else              { W = Wb; r = j - 128; }
        sW[idx] = W[r*CD + kk];
    }
    int j0 = tx, j1 = tx + 96;
    float bias0 = (j0 < 64) ? bc[j0] : ((j0 < 128) ? bf[j0-64] : bb[j0-128]);
    float bias1 = (j1 < 128) ? bf[j1-64] : bb[j1-128];
    float* sXt = sX + ty*512;

    for (int g = blockIdx.x; g < NN/16; g += gridDim.x) {
        int n0 = (g*2 + ty) * 8;
        __syncthreads();
        const float4* x4 = (const float4*)(x + (size_t)n0*64);
        for (int i = tx; i < 128; i += 96) {
            float4 v = x4[i];
            int nl = i >> 4, k4 = (i & 15) * 4;
            sXt[(k4+0)*8 + nl] = v.x;
            sXt[(k4+1)*8 + nl] = v.y;
            sXt[(k4+2)*8 + nl] = v.z;
            sXt[(k4+3)*8 + nl] = v.w;
        }
        __syncthreads();

        float2 ad0[4], ad1[4], as0[4], as1[4];
        #pragma unroll
        for (int p = 0; p < 4; p++) {
            ad0[p] = make_float2(0.f,0.f); ad1[p] = make_float2(0.f,0.f);
            as0[p] = make_float2(0.f,0.f); as1[p] = make_float2(0.f,0.f);
        }
        #pragma unroll 8
        for (int k = 0; k < 64; k++) {
            float wd0 = sW[k*384 + j0];
            float wd1 = sW[k*384 + j1];
            float ws0 = sW[k*384 + 192 + j0];
            float ws1 = sW[k*384 + 192 + j1];
            float2 Wd0 = make_float2(wd0, wd0), Wd1 = make_float2(wd1, wd1);
            float2 Ws0 = make_float2(ws0, ws0), Ws1 = make_float2(ws1, ws1);
            const float2* xp = (const float2*)(sXt + k*8);
            #pragma unroll
            for (int p = 0; p < 4; p++) {
                float2 xv = xp[p];
                ffma2(ad0[p], xv, Wd0);
                ffma2(ad1[p], xv, Wd1);
                ffma2(as0[p], xv, Ws0);
                ffma2(as1[p], xv, Ws1);
            }
        }
        #pragma unroll
        for (int p = 0; p < 4; p++) {
            size_t na = (size_t)(n0 + 2*p)*CD, nb = na + CD;
            g_PDh[na + j0] = __float2half_rn(ad0[p].x + bias0);
            g_PDh[nb + j0] = __float2half_rn(ad0[p].y + bias0);
            g_PDh[na + j1] = __float2half_rn(ad1[p].x + bias1);
            g_PDh[nb + j1] = __float2half_rn(ad1[p].y + bias1);
            g_PSh[na + j0] = __float2half_rn(as0[p].x);
            g_PSh[nb + j0] = __float2half_rn(as0[p].y);
            g_PSh[na + j1] = __float2half_rn(as1[p].x);
            g_PSh[nb + j1] = __float2half_rn(as1[p].y);
        }
    }
}

// ---------------- K2: edge GEMM via HMMA, cp.async double-buffered ---------
// Tile: M=32 edges, N=192, K=64. 8 warps = 2(m) x 4(n); warp = m16 x n48.
// smem byte offsets
#define SW_OFF   0
#define SW_BYTES (192*32*4)               // 24576: W fp16 [n][64k] as u32
#define EA_STRIDE 272                     // 64 floats + 16B pad
#define EA_BYTES (32*EA_STRIDE)           // 8704, fp32 ea tile
#define PD_STRIDE 400                     // 192 halves + 16B pad
#define PD_BYTES (32*PD_STRIDE)           // 12800
#define EA_OFF(b)  (SW_BYTES + (b)*EA_BYTES)
#define PD_OFF(b)  (SW_BYTES + 2*EA_BYTES + (b)*PD_BYTES)
#define PS_OFF(b)  (SW_BYTES + 2*EA_BYTES + 2*PD_BYTES + (b)*PD_BYTES)
#define K2_SMEM    (SW_BYTES + 2*EA_BYTES + 4*PD_BYTES)

__global__ void __launch_bounds__(256, 2)
k2_edge(const float* __restrict__ ea,
        const void* __restrict__ eidx_raw,
        const float* __restrict__ Wc,
        const float* __restrict__ Wf,
        const float* __restrict__ Wb)
{
    extern __shared__ char smc[];
    unsigned* sW32 = (unsigned*)(smc + SW_OFF);
    unsigned smb = smem_u32(smc);
    int tid = threadIdx.x;
    int w   = tid >> 5, lane = tid & 31;
    int gq  = lane >> 2, tl = lane & 3;
    int mb  = (w & 1) * 16;
    int nb  = (w >> 1) * 48;
    int is64 = g_is64;

    // Stage W_edge -> smem fp16 [n][k]
    for (int i = tid; i < 192*32; i += 256) {
        int n = i >> 5, k2 = i & 31;
        const float* W; int r;
        if (n < 64)       { W = Wc; r = n; }
        else if (n < 128) { W = Wf; r = n - 64; }
        else              { W = Wb; r = n - 128; }
        float2 v = *(const float2*)(W + (size_t)r*CD + 128 + 2*k2);
        __half2 h = __floats2half2_rn(v.x, v.y);
        sW32[n*32 + k2] = *(unsigned*)&h;
    }
    __syncthreads();

    unsigned Bf[6][4][2];
    #pragma unroll
    for (int nt = 0; nt < 6; nt++) {
        int n = nb + nt*8 + gq;
        #pragma unroll
        for (int ks = 0; ks < 4; ks++) {
            Bf[nt][ks][0] = sW32[n*32 + ks*8 + tl];
            Bf[nt][ks][1] = sW32[n*32 + ks*8 + tl + 4];
        }
    }
    __syncthreads();

    float sS[12], sQ[12];
    #pragma unroll
    for (int i = 0; i < 12; i++) { sS[i] = 0.f; sQ[i] = 0.f; }

    const int NT = NE / 32;   // 37500

    // ---- staging lambda (cp.async) ----
    auto stage = [&](int buf, int tile) {
        int ebase = tile * 32;
        #pragma unroll
        for (int i = 0; i < 2; i++) {           // ea: 32 rows x 16 chunks
            int f = tid + i*256;
            int r = f >> 4, c = f & 15;
            cpa16(smb + EA_OFF(buf) + r*EA_STRIDE + c*16,
                  ea + (size_t)(ebase+r)*64 + c*4);
        }
        #pragma unroll
        for (int i = 0; i < 3; i++) {           // PD/PS: 32 rows x 24 chunks
            int f = tid + i*256;
            int r = f / 24, c = f - r*24;
            int e = ebase + r;
            int dst;
            if (is64) dst = (int)((const long long*)eidx_raw)[(size_t)NE + e];
            else      dst = ((const int*)eidx_raw)[(size_t)NE + e];
            int src = e / 12;
            cpa16(smb + PD_OFF(buf) + r*PD_STRIDE + c*16,
                  g_PDh + (size_t)dst*CD + c*8);
            cpa16(smb + PS_OFF(buf) + r*PD_STRIDE + c*16,
                  g_PSh + (size_t)src*CD + c*8);
        }
    };

    int t = blockIdx.x;
    int cur = 0;
    if (t < NT) { stage(0, t); }
    cpa_commit();

    while (t < NT) {
        int tn = t + gridDim.x;
        if (tn < NT) stage(cur ^ 1, tn);
        cpa_commit();
        cpa_wait1();
        __syncthreads();

        // ---- compute from buffer cur ----
        int ebase = t * 32;
        const float* eaB = (const float*)(smc + EA_OFF(cur));
        const __half* pdB = (const __half*)(smc + PD_OFF(cur));
        const __half* psB = (const __half*)(smc + PS_OFF(cur));

        float C[6][4];
        #pragma unroll
        for (int nt = 0; nt < 6; nt++)
            #pragma unroll
            for (int q = 0; q < 4; q++) C[nt][q] = 0.f;

        #pragma unroll
        for (int ks = 0; ks < 4; ks++) {
            unsigned A[4];
            {
                float2 v0 = *(const float2*)(eaB + (mb+gq)*68   + 2*(ks*8+tl));
                float2 v1 = *(const float2*)(eaB + (mb+gq+8)*68 + 2*(ks*8+tl));
                float2 v2 = *(const float2*)(eaB + (mb+gq)*68   + 2*(ks*8+tl+4));
                float2 v3 = *(const float2*)(eaB + (mb+gq+8)*68 + 2*(ks*8+tl+4));
                __half2 h0 = __floats2half2_rn(v0.x, v0.y);
                __half2 h1 = __floats2half2_rn(v1.x, v1.y);
                __half2 h2 = __floats2half2_rn(v2.x, v2.y);
                __half2 h3 = __floats2half2_rn(v3.x, v3.y);
                A[0] = *(unsigned*)&h0;
                A[1] = *(unsigned*)&h1;
                A[2] = *(unsigned*)&h2;
                A[3] = *(unsigned*)&h3;
            }
            #pragma unroll
            for (int nt = 0; nt < 6; nt++)
                mma16816(C[nt], A, Bf[nt][ks]);
        }

        int r0 = mb + gq, r1 = r0 + 8;
        size_t e0 = (size_t)(ebase + r0) * CD;
        size_t e1 = (size_t)(ebase + r1) * CD;
        #pragma unroll
        for (int nt = 0; nt < 6; nt++) {
            int col = nb + nt*8 + 2*tl;
            float2 pd0 = __half22float2(*(const __half2*)(pdB + r0*200 + col));
            float2 pd1 = __half22float2(*(const __half2*)(pdB + r1*200 + col));
            float2 ps0 = __half22float2(*(const __half2*)(psB + r0*200 + col));
            float2 ps1 = __half22float2(*(const __half2*)(psB + r1*200 + col));
            float u0x = C[nt][0] + pd0.x + ps0.x, u0y = C[nt][1] + pd0.y + ps0.y;
            float u1x = C[nt][2] + pd1.x + ps1.x, u1y = C[nt][3] + pd1.y + ps1.y;
            __half2 h0 = __floats2half2_rn(u0x, u0y);
            __half2 h1 = __floats2half2_rn(u1x, u1y);
            *(__half2*)(g_Uh + e0 + col) = h0;
            *(__half2*)(g_Uh + e1 + col) = h1;
            sS[nt*2]   += u0x + u1x;
            sQ[nt*2]   += u0x*u0x + u1x*u1x;
            sS[nt*2+1] += u0y + u1y;
            sQ[nt*2+1] += u0y*u0y + u1y*u1y;
        }
        __syncthreads();
        cur ^= 1;
        t = tn;
    }

    #pragma unroll
    for (int i = 0; i < 12; i++) {
        sS[i] += __shfl_xor_sync(0xffffffff, sS[i], 4);
        sS[i] += __shfl_xor_sync(0xffffffff, sS[i], 8);
        sS[i] += __shfl_xor_sync(0xffffffff, sS[i], 16);
        sQ[i] += __shfl_xor_sync(0xffffffff, sQ[i], 4);
        sQ[i] += __shfl_xor_sync(0xffffffff, sQ[i], 8);
        sQ[i] += __shfl_xor_sync(0xffffffff, sQ[i], 16);
    }
    if (lane < 4) {
        int bin = blockIdx.x & (NBINS - 1);
        #pragma unroll
        for (int nt = 0; nt < 6; nt++) {
            int col = nb + nt*8 + 2*lane;
            atomicAdd(&g_binS[(size_t)col*NBINS + bin],     sS[nt*2]);
            atomicAdd(&g_binQ[(size_t)col*NBINS + bin],     sQ[nt*2]);
            atomicAdd(&g_binS[(size_t)(col+1)*NBINS + bin], sS[nt*2+1]);
            atomicAdd(&g_binQ[(size_t)(col+1)*NBINS + bin], sQ[nt*2+1]);
        }
    }
}

// ---------------- K3: parallel reduce -> edge-BN scale/shift ----------
__global__ void k3_reduce(const float* __restrict__ g1, const float* __restrict__ be1,
                          const float* __restrict__ g2, const float* __restrict__ be2,
                          const float* __restrict__ g3, const float* __restrict__ be3)
{
    __shared__ float sS[256], sQ[256];
    int j = blockIdx.x, t = threadIdx.x;
    float S = 0.f, Q = 0.f;
    for (int b = t; b < NBINS; b += 256) {
        S += g_binS[(size_t)j*NBINS + b];
        Q += g_binQ[(size_t)j*NBINS + b];
    }
    sS[t] = S; sQ[t] = Q;
    __syncthreads();
    for (int o = 128; o > 0; o >>= 1) {
        if (t < o) { sS[t] += sS[t+o]; sQ[t] += sQ[t+o]; }
        __syncthreads();
    }
    if (t == 0) {
        float mean = sS[0] / (float)NE;
        float var  = sQ[0] / (float)NE - mean*mean;
        float g, be;
        if (j < 64)       { g = g1[j];     be = be1[j]; }
        else if (j < 128) { g = g2[j-64];  be = be2[j-64]; }
        else              { g = g3[j-128]; be = be3[j-128]; }
        float sc = g * rsqrtf(var + BN_EPS);
        g_scale[j] = sc;
        g_shift[j] = be - mean * sc;
    }
}

// ---------------- K4: warp-per-node apply, no smem, no syncs --------------
__global__ void k4_apply(const float* __restrict__ ea, float* __restrict__ bond_out)
{
    int lane = threadIdx.x & 31;
    int gw   = (blockIdx.x * blockDim.x + threadIdx.x) >> 5;
    int nw   = (gridDim.x * blockDim.x) >> 5;
    int c2   = 2*lane;

    float2 scF = *(const float2*)(g_scale + c2);
    float2 shF = *(const float2*)(g_shift + c2);
    float2 scC = *(const float2*)(g_scale + 64 + c2);
    float2 shC = *(const float2*)(g_shift + 64 + c2);
    float2 scB = *(const float2*)(g_scale + 128 + c2);
    float2 shB = *(const float2*)(g_shift + 128 + c2);

    float2 sS = make_float2(0.f, 0.f), sQ = make_float2(0.f, 0.f);

    for (int n = gw; n < NN; n += nw) {
        int e0 = n * NNBR;
        float2 acc = make_float2(0.f, 0.f);
        #pragma unroll
        for (int el = 0; el < 12; el++) {
            size_t base = (size_t)(e0 + el) * CD;
            float2 f = __half22float2(*(const __half2*)(g_Uh + base + c2));
            float2 c = __half22float2(*(const __half2*)(g_Uh + base + 64 + c2));
            float2 b = __half22float2(*(const __half2*)(g_Uh + base + 128 + c2));
            float vfx = fmaf(f.x, scF.x, shF.x), vfy = fmaf(f.y, scF.y, shF.y);
            float vcx = fmaf(c.x, scC.x, shC.x), vcy = fmaf(c.y, scC.y, shC.y);
            float vbx = fmaf(b.x, scB.x, shB.x), vby = fmaf(b.y, scB.y, shB.y);
            acc.x += sigmoid_f(vfx) * softplus_f(vcx);
            acc.y += sigmoid_f(vfy) * softplus_f(vcy);
            const float2 eav = *(const float2*)(ea + (size_t)(e0+el)*64 + c2);
            float2 bo;
            bo.x = softplus_f(eav.x + vbx);
            bo.y = softplus_f(eav.y + vby);
            *(float2*)(bond_out + (size_t)(e0+el)*64 + c2) = bo;
        }
        *(float2*)(g_nbr + (size_t)n*64 + c2) = acc;
        sS.x += acc.x; sQ.x += acc.x*acc.x;
        sS.y += acc.y; sQ.y += acc.y*acc.y;
    }
    int bin = gw & (NB4 - 1);
    atomicAdd(&g_b4S[(c2)*NB4 + bin],   sS.x);
    atomicAdd(&g_b4Q[(c2)*NB4 + bin],   sQ.x);
    atomicAdd(&g_b4S[(c2+1)*NB4 + bin], sS.y);
    atomicAdd(&g_b4Q[(c2+1)*NB4 + bin], sQ.y);
}

// ---------------- K5: parallel reduce node-BN ----------------
__global__ void k5_reduce(const float* __restrict__ g4, const float* __restrict__ be4)
{
    __shared__ float sS[256], sQ[256];
    int j = blockIdx.x, t = threadIdx.x;
    float S = (t < NB4) ? g_b4S[j*NB4 + t] : 0.f;
    float Q = (t < NB4) ? g_b4Q[j*NB4 + t] : 0.f;
    sS[t] = S; sQ[t] = Q;
    __syncthreads();
    for (int o = 128; o > 0; o >>= 1) {
        if (t < o) { sS[t] += sS[t+o]; sQ[t] += sQ[t+o]; }
        __syncthreads();
    }
    if (t == 0) {
        float mean = sS[0] / (float)NN;
        float var  = sQ[0] / (float)NN - mean*mean;
        float sc = g4[j] * rsqrtf(var + BN_EPS);
        g_scale4[j] = sc;
        g_shift4[j] = be4[j] - mean * sc;
    }
}

// ---------------- K6: out = softplus(x + bn4(nbr_sum)) ----------------
__global__ void k6_out(const float* __restrict__ x, float* __restrict__ out)
{
    int i = blockIdx.x * 256 + threadIdx.x;
    if (i < NN*64) {
        int j = i & 63;
        float v = x[i] + fmaf(g_nbr[i], g_scale4[j], g_shift4[j]);
        out[i] = softplus_f(v);
    }
}

extern "C" void kernel_launch(void* const* d_in, const int* in_sizes, int n_in,
                              void* d_out, int out_size)
{
    const float* x   = (const float*)d_in[0];
    const void*  ei  = (const void*)d_in[1];
    const float* ea  = (const float*)d_in[2];
    const float* Wc  = (const float*)d_in[3];
    const float* bc  = (const float*)d_in[4];
    const float* Wf  = (const float*)d_in[5];
    const float* bf  = (const float*)d_in[6];
    const float* Wb  = (const float*)d_in[7];
    const float* bb  = (const float*)d_in[8];
    const float* g1  = (const float*)d_in[9];
    const float* be1 = (const float*)d_in[10];
    const float* g2  = (const float*)d_in[11];
    const float* be2 = (const float*)d_in[12];
    const float* g3  = (const float*)d_in[13];
    const float* be3 = (const float*)d_in[14];
    const float* g4  = (const float*)d_in[15];
    const float* be4 = (const float*)d_in[16];

    float* out  = (float*)d_out;
    float* bond = out + (size_t)NN * 64;

    cudaFuncSetAttribute(k1_nodegemm, cudaFuncAttributeMaxDynamicSharedMemorySize, K1_SMEM);
    cudaFuncSetAttribute(k2_edge,     cudaFuncAttributeMaxDynamicSharedMemorySize, K2_SMEM);

    k1_nodegemm<<<K1G, dim3(96,2,1), K1_SMEM>>>(x, (const int*)ei, Wc, bc, Wf, bf, Wb, bb);
    k2_edge<<<K2G, 256, K2_SMEM>>>(ea, ei, Wc, Wf, Wb);
    k3_reduce<<<CD, 256>>>(g1, be1, g2, be2, g3, be3);
    k4_apply<<<K4G, 256>>>(ea, bond);
    k5_reduce<<<KD, 256>>>(g4, be4);
    k6_out<<<(NN*64 + 255)/256, 256>>>(x, out);
}